// round 10
// baseline (speedup 1.0000x reference)
#include <cuda_runtime.h>
#include <cstddef>

// ---------------------------------------------------------------------------
// StockPredictor: 2-layer LSTM (B=256, T=2048, D=1, H1=128, H2=64) + FC head.
// R10: all-148-SM producer/consumer pipeline with mixed batch counts.
//   Producers (86 blocks): 84 x 3 batches + 2 x 2.  Layer 1.
//   Consumers (62 blocks): 8 x 5 batches + 54 x 4.  Layer 2 + FC head.
// Per-batch flags; release/acquire through L2; end handshake resets state.
// ---------------------------------------------------------------------------

constexpr int T  = 2048;
constexpr int B  = 256;
constexpr int H1 = 128;
constexpr int G1 = 512;
constexpr int H2 = 64;
constexpr int G2 = 256;

constexpr int NP = 86;         // producer blocks (84 x 3 + 2 x 2)
constexpr int NC = 62;         // consumer blocks (8 x 5 + 54 x 4)

// producer weight split: smem cols [0,56), reg cols [56,128)
constexpr int P_SCOLS = 56;
constexpr int P_PITCH = 60;    // 15*16B odd -> conflict-free LDS.128
// consumer: concat row [0,160) in regs, [160,192) in smem
constexpr int C_PITCH = 36;    // 9*16B odd

// producer smem (NB=3 worst case), floats:
//   Ws 512*60 = 30720 | xs 3*2048 = 6144 | hs 3*128 = 384 | gs 3*512 = 1536
constexpr size_t SMEM_BYTES = (size_t)(30720 + 6144 + 384 + 1536) * 4; // 155136

__device__ float g_h1seq[(size_t)B * T * H1];
__device__ int   g_flag[B];
__device__ int   g_done[B];

// ---------------------------------------------------------------------------
__device__ __forceinline__ void fma2(unsigned long long& acc,
                                     unsigned long long a,
                                     unsigned long long b) {
    asm("fma.rn.f32x2 %0, %1, %2, %0;" : "+l"(acc) : "l"(a), "l"(b));
}
__device__ __forceinline__ float f32x2_sum2(unsigned long long u,
                                            unsigned long long v) {
    unsigned long long s;
    asm("add.rn.f32x2 %0, %1, %2;" : "=l"(s) : "l"(u), "l"(v));
    float lo, hi;
    asm("mov.b64 {%0, %1}, %2;" : "=f"(lo), "=f"(hi) : "l"(s));
    return lo + hi;
}
__device__ __forceinline__ float sigmoid_fast(float x) {
    return __fdividef(1.0f, 1.0f + __expf(-x));
}
__device__ __forceinline__ float tanh_acc(float x) {
    return fmaf(2.0f, sigmoid_fast(2.0f * x), -1.0f);
}
__device__ __forceinline__ int ld_acquire(const int* p) {
    int v;
    asm volatile("ld.acquire.gpu.global.b32 %0, [%1];" : "=r"(v) : "l"(p) : "memory");
    return v;
}
__device__ __forceinline__ void st_release(int* p, int v) {
    asm volatile("st.release.gpu.global.b32 [%0], %1;" :: "l"(p), "r"(v) : "memory");
}

// ---------------------------------------------------------------------------
// PRODUCER: layer 1, NB batch elems, 256 threads, rows rA=tid, rB=tid+256.
// ---------------------------------------------------------------------------
template <int NB>
__device__ __forceinline__ void producer_body(
    float* sm, int bg,
    const float* __restrict__ x,
    const float* __restrict__ W_ih1,
    const float* __restrict__ W_hh1,
    const float* __restrict__ b_ih1,
    const float* __restrict__ b_hh1)
{
    float* Ws = sm;                      // [512][P_PITCH] cols [0,56)
    float* xs = Ws + G1 * P_PITCH;       // [NB][T]
    float* hs = xs + NB * T;             // [NB][H1]
    float* gs = hs + NB * H1;            // [NB][G1]

    const int tid = threadIdx.x;
    const int rA = tid, rB = tid + 256;

    for (int i = tid; i < G1 * P_SCOLS; i += 256) {
        int r = i / P_SCOLS, c = i - r * P_SCOLS;
        Ws[r * P_PITCH + c] = W_hh1[r * H1 + c];
    }
    // reg weights: cols [56,128) = 72 floats = 18 u2 per row
    ulonglong2 wrA[18], wrB[18];
    {
        const ulonglong2* sA = reinterpret_cast<const ulonglong2*>(W_hh1 + rA * H1 + P_SCOLS);
        const ulonglong2* sB = reinterpret_cast<const ulonglong2*>(W_hh1 + rB * H1 + P_SCOLS);
        #pragma unroll
        for (int j = 0; j < 18; j++) { wrA[j] = sA[j]; wrB[j] = sB[j]; }
    }
    const float wxA = W_ih1[rA], wxB = W_ih1[rB];
    const float bA  = b_ih1[rA] + b_hh1[rA];
    const float bB  = b_ih1[rB] + b_hh1[rB];

    for (int i = tid; i < NB * T; i += 256)
        xs[i] = x[(size_t)bg * T + i];
    for (int i = tid; i < NB * H1; i += 256)
        hs[i] = 0.0f;
    __syncthreads();

    float cst0 = 0.0f, cst1 = 0.0f;
    const bool has2 = (tid + 256) < NB * H1;
    const bool isgB = (tid < 128);   // rB in [256,384) -> g gate

    const ulonglong2* wsA = reinterpret_cast<const ulonglong2*>(Ws + rA * P_PITCH);
    const ulonglong2* wsB = reinterpret_cast<const ulonglong2*>(Ws + rB * P_PITCH);

    for (int t = 0; t < T; t++) {
        unsigned long long accA[2 * NB], accB[2 * NB];
        #pragma unroll
        for (int j = 0; j < 2 * NB; j++) { accA[j] = 0ull; accB[j] = 0ull; }

        #pragma unroll
        for (int i = 0; i < P_SCOLS / 4; i++) {           // cols [0,56), smem w
            ulonglong2 wa = wsA[i], wb = wsB[i];
            #pragma unroll
            for (int bb = 0; bb < NB; bb++) {
                ulonglong2 q = reinterpret_cast<const ulonglong2*>(hs + bb * H1)[i];
                fma2(accA[2 * bb], wa.x, q.x); fma2(accA[2 * bb + 1], wa.y, q.y);
                fma2(accB[2 * bb], wb.x, q.x); fma2(accB[2 * bb + 1], wb.y, q.y);
            }
        }
        #pragma unroll
        for (int i = 0; i < 18; i++) {                    // cols [56,128), reg w
            ulonglong2 wa = wrA[i], wb = wrB[i];
            #pragma unroll
            for (int bb = 0; bb < NB; bb++) {
                ulonglong2 q = reinterpret_cast<const ulonglong2*>(hs + bb * H1 + P_SCOLS)[i];
                fma2(accA[2 * bb], wa.x, q.x); fma2(accA[2 * bb + 1], wa.y, q.y);
                fma2(accB[2 * bb], wb.x, q.x); fma2(accB[2 * bb + 1], wb.y, q.y);
            }
        }

        #pragma unroll
        for (int bb = 0; bb < NB; bb++) {
            float xv = xs[bb * T + t];
            float fA = fmaf(xv, wxA, bA) + f32x2_sum2(accA[2 * bb], accA[2 * bb + 1]);
            float fB = fmaf(xv, wxB, bB) + f32x2_sum2(accB[2 * bb], accB[2 * bb + 1]);
            gs[bb * G1 + rA] = sigmoid_fast(fA);          // rows [0,256): i/f
            gs[bb * G1 + rB] = isgB ? tanh_acc(fB) : sigmoid_fast(fB);
        }
        __syncthreads();

        // update: slot s = bb*128+m ; thread handles s=tid (+256 if present)
        {
            int s = tid;
            int bb = s >> 7, m = s & (H1 - 1);
            const float* gb = gs + bb * G1;
            float i_ = gb[m], f_ = gb[H1 + m], g_ = gb[2 * H1 + m], o_ = gb[3 * H1 + m];
            cst0 = fmaf(f_, cst0, i_ * g_);
            float h = o_ * tanh_acc(cst0);
            hs[s] = h;
            g_h1seq[((size_t)(bg + bb) * T + t) * H1 + m] = h;
        }
        if (has2) {
            int s = tid + 256;
            int bb = s >> 7, m = s & (H1 - 1);
            const float* gb = gs + bb * G1;
            float i_ = gb[m], f_ = gb[H1 + m], g_ = gb[2 * H1 + m], o_ = gb[3 * H1 + m];
            cst1 = fmaf(f_, cst1, i_ * g_);
            float h = o_ * tanh_acc(cst1);
            hs[s] = h;
            g_h1seq[((size_t)(bg + bb) * T + t) * H1 + m] = h;
        }
        __syncthreads();
        if (tid < NB) st_release(&g_flag[bg + tid], t + 1);
    }

    // end handshake: wait for consumers of our batches, then reset for replay
    if (tid < NB) {
        while (ld_acquire(&g_done[bg + tid]) == 0) { }
        g_flag[bg + tid] = 0;
        g_done[bg + tid] = 0;
    }
}

// ---------------------------------------------------------------------------
// CONSUMER: layer 2 + FC head, NB batch elems, 256 threads, row r = tid.
// ---------------------------------------------------------------------------
template <int NB>
__device__ __forceinline__ void consumer_body(
    float* sm, int bg,
    const float* __restrict__ W_ih2,
    const float* __restrict__ W_hh2,
    const float* __restrict__ b_ih2,
    const float* __restrict__ b_hh2,
    const float* __restrict__ W_fc1,
    const float* __restrict__ b_fc1,
    const float* __restrict__ W_fc2,
    const float* __restrict__ b_fc2,
    float* __restrict__ out)
{
    float* Ws2   = sm;                   // [256][C_PITCH] concat cols [160,192)
    float* hcat  = Ws2 + G2 * C_PITCH;   // [NB][192] = h1 | h2
    float* gs2   = hcat + NB * 192;      // [NB][256]
    float* bsm   = gs2 + NB * G2;        // [256]
    float* stage = bsm + G2;             // [NB*32]

    const int tid = threadIdx.x;
    const int r = tid;

    // reg weights: concat [0,160) = W_ih2[r][0:128) + W_hh2[r][0:32)
    ulonglong2 wr[40];
    {
        const ulonglong2* sa = reinterpret_cast<const ulonglong2*>(W_ih2 + r * H1);
        #pragma unroll
        for (int j = 0; j < 32; j++) wr[j] = sa[j];
        const ulonglong2* sb = reinterpret_cast<const ulonglong2*>(W_hh2 + r * H2);
        #pragma unroll
        for (int j = 0; j < 8; j++) wr[32 + j] = sb[j];
    }
    // smem weights: concat [160,192) = W_hh2[r][32:64)
    {
        float* wrow = Ws2 + tid * C_PITCH;
        const float4* src = reinterpret_cast<const float4*>(W_hh2 + r * H2 + 32);
        #pragma unroll
        for (int j = 0; j < 8; j++)
            reinterpret_cast<float4*>(wrow)[j] = src[j];
    }
    bsm[tid] = b_ih2[tid] + b_hh2[tid];
    for (int s = tid; s < NB * H2; s += 256) {
        int bb = s >> 6, m = s & (H2 - 1);
        hcat[bb * 192 + H1 + m] = 0.0f;
    }
    __syncthreads();

    float cst0 = 0.0f, cst1 = 0.0f;
    const bool has2 = (tid + 256) < NB * H2;
    const bool is_g = (r >= 2 * H2) && (r < 3 * H2);
    const ulonglong2* ws = reinterpret_cast<const ulonglong2*>(Ws2 + tid * C_PITCH);

    for (int t = 0; t < T; t++) {
        // stage h1(t): each thread acquires the flag for the batch it loads
        #pragma unroll
        for (int it = 0; it < (NB * H1 + 255) / 256; it++) {
            int s = tid + it * 256;
            if (s < NB * H1) {
                int bb = s >> 7, m = s & (H1 - 1);
                while (ld_acquire(&g_flag[bg + bb]) < t + 1) { }
                hcat[bb * 192 + m] =
                    __ldcg(&g_h1seq[((size_t)(bg + bb) * T + t) * H1 + m]);
            }
        }
        __syncthreads();

        unsigned long long acc[2 * NB];
        #pragma unroll
        for (int j = 0; j < 2 * NB; j++) acc[j] = 0ull;

        #pragma unroll
        for (int i = 0; i < 40; i++) {                    // concat [0,160), reg w
            ulonglong2 w = wr[i];
            #pragma unroll
            for (int bb = 0; bb < NB; bb++) {
                ulonglong2 q = reinterpret_cast<const ulonglong2*>(hcat + bb * 192)[i];
                fma2(acc[2 * bb], w.x, q.x); fma2(acc[2 * bb + 1], w.y, q.y);
            }
        }
        #pragma unroll
        for (int i = 0; i < 8; i++) {                     // concat [160,192), smem w
            ulonglong2 w = ws[i];
            #pragma unroll
            for (int bb = 0; bb < NB; bb++) {
                ulonglong2 q = reinterpret_cast<const ulonglong2*>(hcat + bb * 192 + 160)[i];
                fma2(acc[2 * bb], w.x, q.x); fma2(acc[2 * bb + 1], w.y, q.y);
            }
        }

        #pragma unroll
        for (int bb = 0; bb < NB; bb++) {
            float v = bsm[r] + f32x2_sum2(acc[2 * bb], acc[2 * bb + 1]);
            gs2[bb * G2 + r] = is_g ? tanh_acc(v) : sigmoid_fast(v);
        }
        __syncthreads();

        {
            int s = tid;
            if (s < NB * H2) {
                int bb = s >> 6, m = s & (H2 - 1);
                const float* gb = gs2 + bb * G2;
                float i_ = gb[m], f_ = gb[H2 + m], g_ = gb[2 * H2 + m], o_ = gb[3 * H2 + m];
                cst0 = fmaf(f_, cst0, i_ * g_);
                hcat[bb * 192 + H1 + m] = o_ * tanh_acc(cst0);
            }
        }
        if (has2) {
            int s = tid + 256;
            int bb = s >> 6, m = s & (H2 - 1);
            const float* gb = gs2 + bb * G2;
            float i_ = gb[m], f_ = gb[H2 + m], g_ = gb[2 * H2 + m], o_ = gb[3 * H2 + m];
            cst1 = fmaf(f_, cst1, i_ * g_);
            hcat[bb * 192 + H1 + m] = o_ * tanh_acc(cst1);
        }
        __syncthreads();
    }

    // ---- FC head on final h2 ----
    if (tid < NB * 25) {
        int bb = tid / 25;
        int i  = tid - bb * 25;
        float a = b_fc1[i];
        #pragma unroll
        for (int k = 0; k < H2; k++)
            a = fmaf(W_fc1[i * H2 + k], hcat[bb * 192 + H1 + k], a);
        stage[bb * 32 + i] = a;
    }
    __syncthreads();
    if (tid < NB) {
        float a = b_fc2[0];
        #pragma unroll
        for (int i = 0; i < 25; i++)
            a = fmaf(W_fc2[i], stage[tid * 32 + i], a);
        out[bg + tid] = a;
    }
    if (tid < NB) st_release(&g_done[bg + tid], 1);
}

// ---------------------------------------------------------------------------
__global__ __launch_bounds__(256, 1)
void fused_lstm_kernel(const float* __restrict__ x,
                       const float* __restrict__ W_ih1,
                       const float* __restrict__ W_hh1,
                       const float* __restrict__ b_ih1,
                       const float* __restrict__ b_hh1,
                       const float* __restrict__ W_ih2,
                       const float* __restrict__ W_hh2,
                       const float* __restrict__ b_ih2,
                       const float* __restrict__ b_hh2,
                       const float* __restrict__ W_fc1,
                       const float* __restrict__ b_fc1,
                       const float* __restrict__ W_fc2,
                       const float* __restrict__ b_fc2,
                       float* __restrict__ out)
{
    extern __shared__ float sm[];
    const int bid = blockIdx.x;

    if (bid < 84) {
        producer_body<3>(sm, bid * 3, x, W_ih1, W_hh1, b_ih1, b_hh1);
    } else if (bid < NP) {
        producer_body<2>(sm, 252 + (bid - 84) * 2, x, W_ih1, W_hh1, b_ih1, b_hh1);
    } else {
        int cb = bid - NP;
        if (cb < 8)
            consumer_body<5>(sm, cb * 5, W_ih2, W_hh2, b_ih2, b_hh2,
                             W_fc1, b_fc1, W_fc2, b_fc2, out);
        else
            consumer_body<4>(sm, 40 + (cb - 8) * 4, W_ih2, W_hh2, b_ih2, b_hh2,
                             W_fc1, b_fc1, W_fc2, b_fc2, out);
    }
}

// ---------------------------------------------------------------------------
extern "C" void kernel_launch(void* const* d_in, const int* in_sizes, int n_in,
                              void* d_out, int out_size)
{
    const float* x     = (const float*)d_in[0];
    const float* W_ih1 = (const float*)d_in[1];
    const float* W_hh1 = (const float*)d_in[2];
    const float* b_ih1 = (const float*)d_in[3];
    const float* b_hh1 = (const float*)d_in[4];
    const float* W_ih2 = (const float*)d_in[5];
    const float* W_hh2 = (const float*)d_in[6];
    const float* b_ih2 = (const float*)d_in[7];
    const float* b_hh2 = (const float*)d_in[8];
    const float* W_fc1 = (const float*)d_in[9];
    const float* b_fc1 = (const float*)d_in[10];
    const float* W_fc2 = (const float*)d_in[11];
    const float* b_fc2 = (const float*)d_in[12];
    float* out = (float*)d_out;

    static bool attr_done = false;
    if (!attr_done) {
        cudaFuncSetAttribute(fused_lstm_kernel,
                             cudaFuncAttributeMaxDynamicSharedMemorySize, (int)SMEM_BYTES);
        attr_done = true;
    }

    fused_lstm_kernel<<<NP + NC, 256, SMEM_BYTES>>>(
        x, W_ih1, W_hh1, b_ih1, b_hh1,
        W_ih2, W_hh2, b_ih2, b_hh2,
        W_fc1, b_fc1, W_fc2, b_fc2, out);
}